// round 12
// baseline (speedup 1.0000x reference)
#include <cuda_runtime.h>
#include <cuda_bf16.h>

#define N_NODES 100000
#define N_EDGES 500000
#define HIDDEN 32
#define HEADS 4
#define PROJ 128   // HIDDEN*HEADS
#define LN_EPS 1e-5f
#define CAP 48     // bucket slots/node; max degree ~20 (Binomial(500k,1e-5))

#define FILL_BLOCKS ((N_EDGES / 4 + 255) / 256)   // 489
#define PACK_GROUPS (N_NODES / 4)                 // 25000
#define PACK_BLOCKS ((PACK_GROUPS + 255) / 256)   // 98
#define K1_GRID (3 + FILL_BLOCKS + PACK_BLOCKS)   // 590

#define NODE_GRID ((N_NODES * 4 + 255) / 256)     // 4 threads per node

// ---------------- scratch (static device globals; no runtime alloc) ----------
// Invariant restored by node_kernel each launch: g_cnt == 0.
__device__ int    g_cnt[N_NODES];            // per-node edge counts (atomic slots)
__device__ int    g_bucket[CAP * N_NODES];   // TRANSPOSED: [slot][node] -> src row
__device__ float4 g_pos4[N_NODES];           // padded positions (16B aligned gather)
__device__ float  g_scoreC[HEADS * 16];      // per head: A[9], u[3], s (all /sqrt(32))
__device__ float  g_M[HIDDEN * 16];          // M^T: [d][h*4 + {mx,my,mz,c}]

// ====== K1: prep (blocks 0-2) + fill (next 489) + pos-pack (last 98) =========
__global__ void __launch_bounds__(256) build_kernel(const float* __restrict__ pos,
                                                    const void* __restrict__ ei_raw,
                                                    const float* __restrict__ Wq,
                                                    const float* __restrict__ bq,
                                                    const float* __restrict__ Wk,
                                                    const float* __restrict__ bk,
                                                    const float* __restrict__ Wv,
                                                    const float* __restrict__ bv,
                                                    const float* __restrict__ Wout) {
    unsigned b = blockIdx.x;

    if (b < 3) {
        const float invs = 0.17677669529663687f;  // 1/sqrt(32)
        int t = b * 256 + threadIdx.x;
        if (t < 512) {
            int d = t >> 4, idx = t & 15, h = idx >> 2, j = idx & 3;
            float acc = 0.f;
            if (j < 3) {
#pragma unroll 8
                for (int dd = 0; dd < 32; dd++)
                    acc += Wv[j * PROJ + h * 32 + dd] * Wout[(h * 32 + dd) * HIDDEN + d];
            } else {
#pragma unroll 8
                for (int dd = 0; dd < 32; dd++)
                    acc += bv[h * 32 + dd] * Wout[(h * 32 + dd) * HIDDEN + d];
            }
            g_M[t] = acc;
        } else if (t < 576) {
            int u = t - 512, h = u >> 4, idx = u & 15;
            float acc = 0.f;
            if (idx < 9) {
                int i = idx / 3, j = idx % 3;
#pragma unroll 8
                for (int d = 0; d < 32; d++)
                    acc += Wq[i * PROJ + h * 32 + d] * Wk[j * PROJ + h * 32 + d];
            } else if (idx < 12) {
                int i = idx - 9;
#pragma unroll 8
                for (int d = 0; d < 32; d++)
                    acc += Wq[i * PROJ + h * 32 + d] * bk[h * 32 + d]
                         + Wk[i * PROJ + h * 32 + d] * bq[h * 32 + d];
            } else if (idx == 12) {
#pragma unroll 8
                for (int d = 0; d < 32; d++)
                    acc += bq[h * 32 + d] * bk[h * 32 + d];
            }
            g_scoreC[u] = acc * invs;
        }
        return;
    }

    if (b < 3u + FILL_BLOCKS) {
        // ---- fill: 4 edges/thread, slot alloc + transposed 4B row store ----
        int lane = threadIdx.x & 31;
        const int* e32 = (const int*)ei_raw;
        unsigned mz = __ballot_sync(0xffffffffu, __ldg(&e32[2 * lane + 1]) != 0);
        bool is64 = (mz == 0);   // int64 LE < 2^31 => odd words all zero

        int quad = (b - 3) * 256 + threadIdx.x;
        if (quad >= N_EDGES / 4) return;

        int row[4], col[4];
        if (is64) {
            const longlong2* eiR = (const longlong2*)ei_raw;
            const longlong2* eiC = (const longlong2*)((const long long*)ei_raw + N_EDGES);
            longlong2 r0 = __ldg(&eiR[2 * quad + 0]);
            longlong2 r1 = __ldg(&eiR[2 * quad + 1]);
            longlong2 c0 = __ldg(&eiC[2 * quad + 0]);
            longlong2 c1 = __ldg(&eiC[2 * quad + 1]);
            row[0] = (int)r0.x; row[1] = (int)r0.y; row[2] = (int)r1.x; row[3] = (int)r1.y;
            col[0] = (int)c0.x; col[1] = (int)c0.y; col[2] = (int)c1.x; col[3] = (int)c1.y;
        } else {
            const int4* eiR = (const int4*)ei_raw;
            const int4* eiC = (const int4*)((const int*)ei_raw + N_EDGES);
            int4 r = __ldg(&eiR[quad]);
            int4 c = __ldg(&eiC[quad]);
            row[0] = r.x; row[1] = r.y; row[2] = r.z; row[3] = r.w;
            col[0] = c.x; col[1] = c.y; col[2] = c.z; col[3] = c.w;
        }
#pragma unroll
        for (int e = 0; e < 4; e++) {
            int slot = atomicAdd(&g_cnt[col[e]], 1);
            if (slot < CAP) g_bucket[slot * N_NODES + col[e]] = row[e];
        }
        return;
    }

    // ---- pos pack: 4 nodes/thread, fully vectorized ----
    int g = (b - 3 - FILL_BLOCKS) * 256 + threadIdx.x;
    if (g >= PACK_GROUPS) return;
    const float4* p4 = (const float4*)pos;
    float4 a = __ldg(&p4[3 * g + 0]);   // n0.x n0.y n0.z n1.x
    float4 bb = __ldg(&p4[3 * g + 1]);  // n1.y n1.z n2.x n2.y
    float4 cc = __ldg(&p4[3 * g + 2]);  // n2.z n3.x n3.y n3.z
    int n = 4 * g;
    g_pos4[n + 0] = make_float4(a.x, a.y, a.z, 0.f);
    g_pos4[n + 1] = make_float4(a.w, bb.x, bb.y, 0.f);
    g_pos4[n + 2] = make_float4(bb.z, bb.w, cc.x, 0.f);
    g_pos4[n + 3] = make_float4(cc.y, cc.z, cc.w, 0.f);
}

// ====== K2: node kernel — 4 cooperative lanes per node =======================
// sub = tid & 3 handles bucket slots {sub, sub+4, ...} (divergence = max
// ceil(deg/4) instead of max deg), then 4-lane shuffle-combines acc[16],
// computes 8 of the 32 output dims (single pass, o in regs), 4-lane combines
// LN stats, and stores its 8 outputs (128B/node fully coalesced).
__global__ void __launch_bounds__(256, 4) node_kernel(float* __restrict__ out,
                                                      const float* __restrict__ bout,
                                                      const float* __restrict__ gamma,
                                                      const float* __restrict__ beta) {
    __shared__ __align__(16) float sM[512];   // M^T: [d][16]
    __shared__ __align__(16) float sSc[64];
    __shared__ float sB[32], sG[32], sBe[32];
    int t = threadIdx.x;
    for (int i = t; i < 512; i += blockDim.x) sM[i] = g_M[i];
    if (t < 64) sSc[t] = g_scoreC[t];
    if (t < 32) { sB[t] = __ldg(&bout[t]); sG[t] = __ldg(&gamma[t]); sBe[t] = __ldg(&beta[t]); }
    __syncthreads();

    int gtid = blockIdx.x * blockDim.x + t;
    int node = gtid >> 2;
    int sub  = gtid & 3;
    if (node >= N_NODES) return;

    int c = g_cnt[node];                 // broadcast read across the 4 lanes
    if (sub == 0) g_cnt[node] = 0;       // restore invariant (after the read)
    int cc = min(c, CAP);

    float4 pme = g_pos4[node];
    float acc[16];
#pragma unroll
    for (int q = 0; q < 16; q++) acc[q] = 0.f;

    // each lane replays slots sub, sub+4, sub+8, ... (2 per loop trip)
    for (int i = sub; i < cc; i += 8) {
        int i1 = i + 4;
        int r0 = g_bucket[i * N_NODES + node];
        int r1 = (i1 < cc) ? g_bucket[i1 * N_NODES + node] : r0;
        float4 p0 = g_pos4[r0];
        float4 p1 = g_pos4[r1];
#pragma unroll
        for (int k = 0; k < 2; k++) {
            if (k == 1 && i1 >= cc) break;
            float4 pk = (k == 0) ? p0 : p1;
            float x = pk.x - pme.x;
            float y = pk.y - pme.y;
            float z = pk.z - pme.z;
            float sc[HEADS];
            float sum = 0.f;
#pragma unroll
            for (int h = 0; h < HEADS; h++) {
                const float* cf = &sSc[16 * h];
                float t0 = cf[0] * x + cf[1] * y + cf[2] * z;
                float t1 = cf[3] * x + cf[4] * y + cf[5] * z;
                float t2 = cf[6] * x + cf[7] * y + cf[8] * z;
                float s = x * t0 + y * t1 + z * t2
                        + cf[9] * x + cf[10] * y + cf[11] * z + cf[12];
                sc[h] = __expf(s);
                sum += sc[h];
            }
            float inv = 1.f / sum;
#pragma unroll
            for (int h = 0; h < HEADS; h++) {
                float a = sc[h] * inv;
                acc[4 * h + 0] += a * x;
                acc[4 * h + 1] += a * y;
                acc[4 * h + 2] += a * z;
                acc[4 * h + 3] += a;
            }
        }
    }

    // combine acc across the 4 lanes of this node (butterfly xor 1, 2)
#pragma unroll
    for (int q = 0; q < 16; q++) {
        acc[q] += __shfl_xor_sync(0xffffffffu, acc[q], 1);
        acc[q] += __shfl_xor_sync(0xffffffffu, acc[q], 2);
    }

    float invc = 1.f / (float)max(c, 1);
#pragma unroll
    for (int q = 0; q < 16; q++) acc[q] *= invc;

    // fold: this lane computes output dims d = sub*8 .. sub*8+7 (single pass)
    const float4* sM4 = (const float4*)sM;
    float o[8];
    float psum = 0.f, psq = 0.f;
#pragma unroll
    for (int dd = 0; dd < 8; dd++) {
        int d = sub * 8 + dd;
        float4 m0 = sM4[d * 4 + 0];
        float4 m1 = sM4[d * 4 + 1];
        float4 m2 = sM4[d * 4 + 2];
        float4 m3 = sM4[d * 4 + 3];
        float v = acc[0] * m0.x + acc[1] * m0.y + acc[2] * m0.z + acc[3] * m0.w
                + acc[4] * m1.x + acc[5] * m1.y + acc[6] * m1.z + acc[7] * m1.w
                + acc[8] * m2.x + acc[9] * m2.y + acc[10] * m2.z + acc[11] * m2.w
                + acc[12] * m3.x + acc[13] * m3.y + acc[14] * m3.z + acc[15] * m3.w
                + sB[d];
        o[dd] = v;
        psum += v;
        psq += v * v;
    }
    // LN stats across the 4 lanes
    psum += __shfl_xor_sync(0xffffffffu, psum, 1);
    psum += __shfl_xor_sync(0xffffffffu, psum, 2);
    psq  += __shfl_xor_sync(0xffffffffu, psq, 1);
    psq  += __shfl_xor_sync(0xffffffffu, psq, 2);

    float mean = psum * (1.f / 32.f);
    float var = psq * (1.f / 32.f) - mean * mean;
    float rstd = rsqrtf(fmaxf(var, 0.f) + LN_EPS);

    float4* outp = (float4*)&out[(size_t)node * 32 + sub * 8];
#pragma unroll
    for (int q4 = 0; q4 < 2; q4++) {
        float y[4];
#pragma unroll
        for (int j = 0; j < 4; j++) {
            int dd = q4 * 4 + j;
            int d = sub * 8 + dd;
            float v = (o[dd] - mean) * rstd * sG[d] + sBe[d];
            y[j] = v / (1.f + __expf(-v));
        }
        outp[q4] = make_float4(y[0], y[1], y[2], y[3]);
    }
}

// ---------------- launch ------------------------------------------------------
extern "C" void kernel_launch(void* const* d_in, const int* in_sizes, int n_in,
                              void* d_out, int out_size) {
    const float* pos  = (const float*)d_in[0];
    const void*  ei   = d_in[1];
    const float* Wq   = (const float*)d_in[2];
    const float* bq   = (const float*)d_in[3];
    const float* Wk   = (const float*)d_in[4];
    const float* bk   = (const float*)d_in[5];
    const float* Wv   = (const float*)d_in[6];
    const float* bv   = (const float*)d_in[7];
    const float* Wout = (const float*)d_in[8];
    const float* bout = (const float*)d_in[9];
    const float* gamma= (const float*)d_in[10];
    const float* beta = (const float*)d_in[11];

    build_kernel<<<K1_GRID, 256>>>(pos, ei, Wq, bq, Wk, bk, Wv, bv, Wout);
    node_kernel<<<NODE_GRID, 256>>>((float*)d_out, bout, gamma, beta);
}

// round 13
// speedup vs baseline: 1.4505x; 1.4505x over previous
#include <cuda_runtime.h>
#include <cuda_bf16.h>

#define N_NODES 100000
#define N_EDGES 500000
#define HIDDEN 32
#define HEADS 4
#define PROJ 128   // HIDDEN*HEADS
#define LN_EPS 1e-5f
#define CAP 48     // bucket slots/node; max degree ~20 (Binomial(500k,1e-5))

#define FILL_BLOCKS ((N_EDGES / 4 + 255) / 256)   // 489
#define PACK_GROUPS (N_NODES / 4)                 // 25000
#define PACK_BLOCKS ((PACK_GROUPS + 255) / 256)   // 98
#define K1_GRID (3 + FILL_BLOCKS + PACK_BLOCKS)   // 590

// ---------------- scratch (static device globals; no runtime alloc) ----------
// Invariants: g_cnt reset by node_kernel; g_ccnt reset by build_kernel.
__device__ int    g_cnt[N_NODES];            // per-node edge counts (atomic slots)
__device__ int    g_bucket[CAP * N_NODES];   // TRANSPOSED: [slot][node] -> src row
__device__ float4 g_pos4[N_NODES];           // padded positions (16B aligned gather)
__device__ float  g_scoreC[HEADS * 16];      // per head: A[9], u[3], s (all /sqrt(32))
__device__ float  g_M[HIDDEN * 16];          // M^T: [d][h*4 + {mx,my,mz,c}]
__device__ int    g_ccnt[4];                 // per-degree-class node counts
__device__ int    g_clist[4 * N_NODES];      // class-compacted node lists

// ====== K1: prep (blocks 0-2) + fill (next 489) + pos-pack (last 98) =========
__global__ void __launch_bounds__(256) build_kernel(const float* __restrict__ pos,
                                                    const void* __restrict__ ei_raw,
                                                    const float* __restrict__ Wq,
                                                    const float* __restrict__ bq,
                                                    const float* __restrict__ Wk,
                                                    const float* __restrict__ bk,
                                                    const float* __restrict__ Wv,
                                                    const float* __restrict__ bv,
                                                    const float* __restrict__ Wout) {
    unsigned b = blockIdx.x;

    if (b < 3) {
        if (b == 0 && threadIdx.x >= 252) g_ccnt[threadIdx.x - 252] = 0;  // reset class counters
        const float invs = 0.17677669529663687f;  // 1/sqrt(32)
        int t = b * 256 + threadIdx.x;
        if (t < 512) {
            int d = t >> 4, idx = t & 15, h = idx >> 2, j = idx & 3;
            float acc = 0.f;
            if (j < 3) {
#pragma unroll 8
                for (int dd = 0; dd < 32; dd++)
                    acc += Wv[j * PROJ + h * 32 + dd] * Wout[(h * 32 + dd) * HIDDEN + d];
            } else {
#pragma unroll 8
                for (int dd = 0; dd < 32; dd++)
                    acc += bv[h * 32 + dd] * Wout[(h * 32 + dd) * HIDDEN + d];
            }
            g_M[t] = acc;
        } else if (t < 576) {
            int u = t - 512, h = u >> 4, idx = u & 15;
            float acc = 0.f;
            if (idx < 9) {
                int i = idx / 3, j = idx % 3;
#pragma unroll 8
                for (int d = 0; d < 32; d++)
                    acc += Wq[i * PROJ + h * 32 + d] * Wk[j * PROJ + h * 32 + d];
            } else if (idx < 12) {
                int i = idx - 9;
#pragma unroll 8
                for (int d = 0; d < 32; d++)
                    acc += Wq[i * PROJ + h * 32 + d] * bk[h * 32 + d]
                         + Wk[i * PROJ + h * 32 + d] * bq[h * 32 + d];
            } else if (idx == 12) {
#pragma unroll 8
                for (int d = 0; d < 32; d++)
                    acc += bq[h * 32 + d] * bk[h * 32 + d];
            }
            g_scoreC[u] = acc * invs;
        }
        return;
    }

    if (b < 3u + FILL_BLOCKS) {
        int lane = threadIdx.x & 31;
        const int* e32 = (const int*)ei_raw;
        unsigned mz = __ballot_sync(0xffffffffu, __ldg(&e32[2 * lane + 1]) != 0);
        bool is64 = (mz == 0);   // int64 LE < 2^31 => odd words all zero

        int quad = (b - 3) * 256 + threadIdx.x;
        if (quad >= N_EDGES / 4) return;

        int row[4], col[4];
        if (is64) {
            const longlong2* eiR = (const longlong2*)ei_raw;
            const longlong2* eiC = (const longlong2*)((const long long*)ei_raw + N_EDGES);
            longlong2 r0 = __ldg(&eiR[2 * quad + 0]);
            longlong2 r1 = __ldg(&eiR[2 * quad + 1]);
            longlong2 c0 = __ldg(&eiC[2 * quad + 0]);
            longlong2 c1 = __ldg(&eiC[2 * quad + 1]);
            row[0] = (int)r0.x; row[1] = (int)r0.y; row[2] = (int)r1.x; row[3] = (int)r1.y;
            col[0] = (int)c0.x; col[1] = (int)c0.y; col[2] = (int)c1.x; col[3] = (int)c1.y;
        } else {
            const int4* eiR = (const int4*)ei_raw;
            const int4* eiC = (const int4*)((const int*)ei_raw + N_EDGES);
            int4 r = __ldg(&eiR[quad]);
            int4 c = __ldg(&eiC[quad]);
            row[0] = r.x; row[1] = r.y; row[2] = r.z; row[3] = r.w;
            col[0] = c.x; col[1] = c.y; col[2] = c.z; col[3] = c.w;
        }
#pragma unroll
        for (int e = 0; e < 4; e++) {
            int slot = atomicAdd(&g_cnt[col[e]], 1);
            if (slot < CAP) g_bucket[slot * N_NODES + col[e]] = row[e];
        }
        return;
    }

    // ---- pos pack: 4 nodes/thread, fully vectorized ----
    int g = (b - 3 - FILL_BLOCKS) * 256 + threadIdx.x;
    if (g >= PACK_GROUPS) return;
    const float4* p4 = (const float4*)pos;
    float4 a = __ldg(&p4[3 * g + 0]);
    float4 bb = __ldg(&p4[3 * g + 1]);
    float4 cc = __ldg(&p4[3 * g + 2]);
    int n = 4 * g;
    g_pos4[n + 0] = make_float4(a.x, a.y, a.z, 0.f);
    g_pos4[n + 1] = make_float4(a.w, bb.x, bb.y, 0.f);
    g_pos4[n + 2] = make_float4(bb.z, bb.w, cc.x, 0.f);
    g_pos4[n + 3] = make_float4(cc.y, cc.z, cc.w, 0.f);
}

// ====== K2: classify — bin nodes by degree into 4 compacted lists ============
__global__ void __launch_bounds__(256) classify_kernel() {
    __shared__ int sCnt[4];
    __shared__ int sBase[4];
    int t = threadIdx.x;
    if (t < 4) sCnt[t] = 0;
    __syncthreads();

    int node = blockIdx.x * 256 + t;
    bool valid = (node < N_NODES);
    int k = 3, rank = 0;
    if (valid) {
        int d = g_cnt[node];
        k = (d <= 4) ? 0 : (d <= 8) ? 1 : (d <= 16) ? 2 : 3;
        rank = atomicAdd(&sCnt[k], 1);
    }
    __syncthreads();
    if (t < 4) sBase[t] = atomicAdd(&g_ccnt[t], sCnt[t]);
    __syncthreads();
    if (valid) g_clist[k * N_NODES + sBase[k] + rank] = node;
}

// ====== K3: node kernel — class-uniform replay + fold + LN + SiLU ============
__device__ __forceinline__ void edge_accum(float x, float y, float z, float m,
                                           const float* cfAll, float* acc) {
    float sc[HEADS];
    float sum = 0.f;
#pragma unroll
    for (int h = 0; h < HEADS; h++) {
        const float* cf = &cfAll[16 * h];
        float t0 = cf[0] * x + cf[1] * y + cf[2] * z;
        float t1 = cf[3] * x + cf[4] * y + cf[5] * z;
        float t2 = cf[6] * x + cf[7] * y + cf[8] * z;
        float s = x * t0 + y * t1 + z * t2
                + cf[9] * x + cf[10] * y + cf[11] * z + cf[12];
        sc[h] = __expf(s);
        sum += sc[h];
    }
    float inv = m / sum;          // m = 0 masks this (fake) edge entirely
#pragma unroll
    for (int h = 0; h < HEADS; h++) {
        float a = sc[h] * inv;
        acc[4 * h + 0] += a * x;
        acc[4 * h + 1] += a * y;
        acc[4 * h + 2] += a * z;
        acc[4 * h + 3] += a;
    }
}

template <int K>
__device__ __forceinline__ void replay_fixed(int node, int deg, float4 pme,
                                             const float* sSc, float* acc) {
    int rows[K];
    float4 p[K];
#pragma unroll
    for (int k = 0; k < K; k++) {
        int r = node;                      // safe self-gather for masked slots
        if (k < deg) r = g_bucket[k * N_NODES + node];
        rows[k] = r;
    }
#pragma unroll
    for (int k = 0; k < K; k++) p[k] = g_pos4[rows[k]];
#pragma unroll
    for (int k = 0; k < K; k++) {
        float m = (k < deg) ? 1.f : 0.f;
        edge_accum(p[k].x - pme.x, p[k].y - pme.y, p[k].z - pme.z, m, sSc, acc);
    }
}

__device__ void replay_dyn(int node, int deg, float4 pme,
                           const float* sSc, float* acc) {
    int cc = min(deg, CAP);
    for (int i = 0; i < cc; i += 8) {
        int rows[8];
        float4 p[8];
#pragma unroll
        for (int k = 0; k < 8; k++) {
            int r = node;
            if (i + k < cc) r = g_bucket[(i + k) * N_NODES + node];
            rows[k] = r;
        }
#pragma unroll
        for (int k = 0; k < 8; k++) p[k] = g_pos4[rows[k]];
#pragma unroll
        for (int k = 0; k < 8; k++) {
            float m = (i + k < cc) ? 1.f : 0.f;
            edge_accum(p[k].x - pme.x, p[k].y - pme.y, p[k].z - pme.z, m, sSc, acc);
        }
    }
}

__global__ void __launch_bounds__(256, 2) node_kernel(float* __restrict__ out,
                                                      const float* __restrict__ bout,
                                                      const float* __restrict__ gamma,
                                                      const float* __restrict__ beta) {
    __shared__ __align__(16) float sM[512];   // M^T: [d][16]
    __shared__ __align__(16) float sSc[64];
    __shared__ float sB[32], sG[32], sBe[32];
    int t = threadIdx.x;
    for (int i = t; i < 512; i += blockDim.x) sM[i] = g_M[i];
    if (t < 64) sSc[t] = g_scoreC[t];
    if (t < 32) { sB[t] = __ldg(&bout[t]); sG[t] = __ldg(&gamma[t]); sBe[t] = __ldg(&beta[t]); }
    __syncthreads();

    int j = blockIdx.x * blockDim.x + t;
    if (j >= N_NODES) return;

    int c0 = g_ccnt[0], c1 = g_ccnt[1], c2 = g_ccnt[2];
    int o1 = c0, o2 = c0 + c1, o3 = c0 + c1 + c2;

    int cls, node;
    if (j < o1)      { cls = 0; node = g_clist[j]; }
    else if (j < o2) { cls = 1; node = g_clist[N_NODES + (j - o1)]; }
    else if (j < o3) { cls = 2; node = g_clist[2 * N_NODES + (j - o2)]; }
    else             { cls = 3; node = g_clist[3 * N_NODES + (j - o3)]; }

    int c = g_cnt[node];
    g_cnt[node] = 0;                     // restore invariant for next replay

    float4 pme = g_pos4[node];
    float acc[16];
#pragma unroll
    for (int q = 0; q < 16; q++) acc[q] = 0.f;

    if (cls == 0)      replay_fixed<4>(node, c, pme, sSc, acc);
    else if (cls == 1) replay_fixed<8>(node, c, pme, sSc, acc);
    else if (cls == 2) replay_fixed<16>(node, c, pme, sSc, acc);
    else               replay_dyn(node, c, pme, sSc, acc);

    float invc = 1.f / (float)max(c, 1);
#pragma unroll
    for (int q = 0; q < 16; q++) acc[q] *= invc;

    const float4* sM4 = (const float4*)sM;
    float o[32];
    float mean = 0.f;
#pragma unroll
    for (int d = 0; d < 32; d++) {
        float4 m0 = sM4[d * 4 + 0];
        float4 m1 = sM4[d * 4 + 1];
        float4 m2 = sM4[d * 4 + 2];
        float4 m3 = sM4[d * 4 + 3];
        float a = acc[0] * m0.x + acc[1] * m0.y + acc[2] * m0.z + acc[3] * m0.w
                + acc[4] * m1.x + acc[5] * m1.y + acc[6] * m1.z + acc[7] * m1.w
                + acc[8] * m2.x + acc[9] * m2.y + acc[10] * m2.z + acc[11] * m2.w
                + acc[12] * m3.x + acc[13] * m3.y + acc[14] * m3.z + acc[15] * m3.w;
        o[d] = a + sB[d];
        mean += o[d];
    }
    mean *= (1.f / 32.f);
    float var = 0.f;
#pragma unroll
    for (int d = 0; d < 32; d++) {
        float dd = o[d] - mean;
        var += dd * dd;
    }
    float rstd = rsqrtf(var * (1.f / 32.f) + LN_EPS);

    float4* outp = (float4*)&out[(size_t)node * 32];
#pragma unroll
    for (int d4 = 0; d4 < 8; d4++) {
        float4 r;
        float y0 = (o[d4*4+0] - mean) * rstd * sG[d4*4+0] + sBe[d4*4+0];
        float y1 = (o[d4*4+1] - mean) * rstd * sG[d4*4+1] + sBe[d4*4+1];
        float y2 = (o[d4*4+2] - mean) * rstd * sG[d4*4+2] + sBe[d4*4+2];
        float y3 = (o[d4*4+3] - mean) * rstd * sG[d4*4+3] + sBe[d4*4+3];
        r.x = y0 / (1.f + __expf(-y0));
        r.y = y1 / (1.f + __expf(-y1));
        r.z = y2 / (1.f + __expf(-y2));
        r.w = y3 / (1.f + __expf(-y3));
        outp[d4] = r;
    }
}

// ---------------- launch ------------------------------------------------------
extern "C" void kernel_launch(void* const* d_in, const int* in_sizes, int n_in,
                              void* d_out, int out_size) {
    const float* pos  = (const float*)d_in[0];
    const void*  ei   = d_in[1];
    const float* Wq   = (const float*)d_in[2];
    const float* bq   = (const float*)d_in[3];
    const float* Wk   = (const float*)d_in[4];
    const float* bk   = (const float*)d_in[5];
    const float* Wv   = (const float*)d_in[6];
    const float* bv   = (const float*)d_in[7];
    const float* Wout = (const float*)d_in[8];
    const float* bout = (const float*)d_in[9];
    const float* gamma= (const float*)d_in[10];
    const float* beta = (const float*)d_in[11];

    build_kernel<<<K1_GRID, 256>>>(pos, ei, Wq, bq, Wk, bk, Wv, bv, Wout);
    classify_kernel<<<(N_NODES + 255) / 256, 256>>>();
    node_kernel<<<(N_NODES + 255) / 256, 256>>>((float*)d_out, bout, gamma, beta);
}